// round 9
// baseline (speedup 1.0000x reference)
#include <cuda_runtime.h>
#include <cuda_fp16.h>
#include <cstdint>
#include <math.h>

// BatchHardTripletLoss: N=8192, D=128, fp32 in, scalar fp32 out.
// Gram on mma.sync fp16 (fp32 acc), single pass: dot = fp16(x)_i . fp16(x)_j
// Rect-tiled upper triangle: tiles are 64 rows (bi in 0..127) x 128 cols
// (bj in 0..63), kept iff bj >= bi/2 -> 4160 tiles, one per CTA.
// Straddle tiles double-cover some transposed pairs: min/max idempotent, OK.
// Dual fold per tile:
//   row-fold: anchors i (64 rows), tv = cj[j] - 2 dot -> slot (bj, sub=wn)
//   col-fold: anchors j (128 cols), tv = cj[i] - 2 dot -> slot (bi>>1, 4+(bi&1))
// Every (slot, anchor) written exactly once -> no init, no atomics.
// Warp tile 32x32 (acc 32 regs) + 50KB smem -> 3 CTAs/SM (24 warps) to
// overlap tensor pipe, fma-pipe epilogue, and staging across warps.

#define NPTS   8192
#define DIM    128
#define MARGIN 0.2f
#define EPSV   1e-6f
#define TILE_M 64
#define TILE_N 128
#define NCTAS  4160
#define NSUB   6

// smem layout (bytes)
#define OFF_A    0               // 16 KB fp16 A tile (64x128)
#define OFF_B    16384           // 32 KB fp16 B tile (128x128); scratch aliases
#define OFF_CJR  49152           // float2[64] row meta (cj, label-as-float)
#define OFF_CJC  49664           // float2[128] col meta
#define SMEM_BYTES 50688
#define SCR9     9               // 8 groups + pad (9 coprime 32 -> conflict-free)
#define SCR_HN_OFF (128 * SCR9 * 4)   // 4608 B

__device__ float g_ci[NPTS];
__device__ float g_cj[NPTS];
__device__ __align__(16) __half g_xh[NPTS * DIM];
__device__ float g_php[64 * NSUB * NPTS];
__device__ float g_phn[64 * NSUB * NPTS];
__device__ float g_bsum[64];
__device__ int   g_cnt = 0;

// ---------------- helpers ----------------
__device__ __forceinline__ uint32_t smem_u32(const void* p) {
    uint32_t a;
    asm("{ .reg .u64 t; cvta.to.shared.u64 t, %1; cvt.u32.u64 %0, t; }" : "=r"(a) : "l"(p));
    return a;
}
// swizzled offset, 128-row x 128-col fp16 tile (chunk c = 16B, 0..15)
__device__ __forceinline__ uint32_t t_off(int r, int c) {
    return (uint32_t)(((r >> 3) << 10) + ((c >> 3) << 14) + ((r & 7) << 7)
                      + (((c & 7) ^ (r & 7)) << 4));
}
// swizzled offset, 64-row x 128-col fp16 tile (compact: c-block stride 8KB)
__device__ __forceinline__ uint32_t a_off(int r, int c) {
    return (uint32_t)(((r >> 3) << 10) + ((c >> 3) << 13) + ((r & 7) << 7)
                      + (((c & 7) ^ (r & 7)) << 4));
}
__device__ __forceinline__ void cp16(uint32_t saddr, const void* gaddr) {
    asm volatile("cp.async.cg.shared.global [%0], [%1], 16;"
                 :: "r"(saddr), "l"(gaddr) : "memory");
}
__device__ __forceinline__ void ldsm4(uint32_t* r, uint32_t addr) {
    asm volatile("ldmatrix.sync.aligned.m8n8.x4.shared.b16 {%0,%1,%2,%3}, [%4];"
                 : "=r"(r[0]), "=r"(r[1]), "=r"(r[2]), "=r"(r[3]) : "r"(addr));
}
__device__ __forceinline__ void mma16816(float* c, const uint32_t* a, const uint32_t* b) {
    asm volatile("mma.sync.aligned.m16n8k16.row.col.f32.f16.f16.f32 "
                 "{%0,%1,%2,%3}, {%4,%5,%6,%7}, {%8,%9}, {%0,%1,%2,%3};"
                 : "+f"(c[0]), "+f"(c[1]), "+f"(c[2]), "+f"(c[3])
                 : "r"(a[0]), "r"(a[1]), "r"(a[2]), "r"(a[3]), "r"(b[0]), "r"(b[1]));
}
// tiles before pair-strip k (k = bi>>1): base(k) = k*(129-k)
__device__ __forceinline__ int pair_base(int k) { return k * (129 - k); }

// ---------------- precompute: ci/cj + fp16 conversion, 4 rows/warp -------
__global__ void precompute_kernel(const float* __restrict__ x) {
    int w = (blockIdx.x * blockDim.x + threadIdx.x) >> 5;
    int lane = threadIdx.x & 31;
    int row0 = w * 4;
    float4 v[4];
    #pragma unroll
    for (int r = 0; r < 4; r++)
        v[r] = *(const float4*)(x + (size_t)(row0 + r) * DIM + lane * 4);
    #pragma unroll
    for (int r = 0; r < 4; r++) {
        int row = row0 + r;
        float sq = v[r].x * v[r].x + v[r].y * v[r].y + v[r].z * v[r].z + v[r].w * v[r].w;
        float s  = v[r].x + v[r].y + v[r].z + v[r].w;
        #pragma unroll
        for (int o = 16; o; o >>= 1) {
            sq += __shfl_xor_sync(0xffffffffu, sq, o);
            s  += __shfl_xor_sync(0xffffffffu, s,  o);
        }
        if (lane == 0) {
            g_ci[row] = sq - 2.0f * EPSV * s;
            g_cj[row] = sq + 2.0f * EPSV * s + (float)DIM * EPSV * EPSV;
        }
        __half2* dh = (__half2*)(g_xh + (size_t)row * DIM + lane * 4);
        dh[0] = __floats2half2_rn(v[r].x, v[r].y);
        dh[1] = __floats2half2_rn(v[r].z, v[r].w);
    }
}

// ---------------- main fused kernel: one 64x128 tile per CTA -------------
__global__ void __launch_bounds__(256, 3)
tile_kernel(const int* __restrict__ tgt) {
    extern __shared__ char smem[];
    const uint32_t sb = smem_u32(smem);
    const int tid  = threadIdx.x;
    const int lane = tid & 31;
    const int wid  = tid >> 5;
    const int wm = wid & 1;          // 2 warp rows (32 each)
    const int wn = wid >> 1;         // 4 warp cols (32 each)
    float2* scjr = (float2*)(smem + OFF_CJR);
    float2* scjc = (float2*)(smem + OFF_CJC);

    // decode tile id -> (bi, bj)
    const int t = blockIdx.x;
    int k = (int)(64.5f - sqrtf(64.5f * 64.5f - (float)t));
    if (k < 0) k = 0; if (k > 63) k = 63;
    while (k < 63 && pair_base(k + 1) <= t) k++;
    while (k > 0 && pair_base(k) > t) k--;
    int rem = t - pair_base(k);
    const int width = 64 - k;
    const int bi = 2 * k + (rem >= width ? 1 : 0);
    const int bj = k + (rem >= width ? rem - width : rem);

    // stage A (16 KB, 64x128) + B (32 KB, 128x128) + meta
    {
        const char* ga = (const char*)(g_xh + (size_t)bi * TILE_M * DIM);
        const char* gb = (const char*)(g_xh + (size_t)bj * TILE_N * DIM);
        #pragma unroll
        for (int it = 0; it < 4; it++) {
            int lin = it * 256 + tid;
            cp16(sb + OFF_A + a_off(lin >> 4, lin & 15), ga + (size_t)lin * 16);
        }
        #pragma unroll
        for (int it = 0; it < 8; it++) {
            int lin = it * 256 + tid;
            cp16(sb + OFF_B + t_off(lin >> 4, lin & 15), gb + (size_t)lin * 16);
        }
        if (tid < TILE_M) {
            int r = bi * TILE_M + tid;
            scjr[tid] = make_float2(g_cj[r], __int_as_float(tgt[r]));
        }
        if (tid < TILE_N) {
            int j = bj * TILE_N + tid;
            scjc[tid] = make_float2(g_cj[j], __int_as_float(tgt[j]));
        }
        asm volatile("cp.async.commit_group;" ::: "memory");
    }

    const int ra_lane = (lane & 15);
    const int ca_add  = (lane >> 4);
    const int rb_lane = ((lane >> 4) << 3) + (lane & 7);
    const int cb_add  = ((lane >> 3) & 1);

    asm volatile("cp.async.wait_group 0;" ::: "memory");
    __syncthreads();

    // ---------------- single-pass MMA over K=128 ----------------
    float acc[2][4][4];
    #pragma unroll
    for (int mt = 0; mt < 2; mt++)
        #pragma unroll
        for (int n8 = 0; n8 < 4; n8++)
            #pragma unroll
            for (int q = 0; q < 4; q++) acc[mt][n8][q] = 0.0f;

    #pragma unroll
    for (int ks = 0; ks < 8; ks++) {
        uint32_t ah[2][4], bh[2][4];
        #pragma unroll
        for (int mt = 0; mt < 2; mt++)
            ldsm4(ah[mt], sb + OFF_A + a_off(wm * 32 + mt * 16 + ra_lane, 2 * ks + ca_add));
        #pragma unroll
        for (int nt = 0; nt < 2; nt++)
            ldsm4(bh[nt], sb + OFF_B + t_off(wn * 32 + nt * 16 + rb_lane, 2 * ks + cb_add));
        #pragma unroll
        for (int mt = 0; mt < 2; mt++)
            #pragma unroll
            for (int nt = 0; nt < 2; nt++) {
                mma16816(acc[mt][2 * nt],     ah[mt], &bh[nt][0]);
                mma16816(acc[mt][2 * nt + 1], ah[mt], &bh[nt][2]);
            }
    }

    __syncthreads();   // all warps done with B before scratch aliasing

    // ---------------- dual-fold epilogue ----------------
    float cjr[2][2];
    int   tir[2][2];
    #pragma unroll
    for (int mt = 0; mt < 2; mt++)
        #pragma unroll
        for (int so = 0; so < 2; so++) {
            float2 q = scjr[wm * 32 + mt * 16 + so * 8 + (lane >> 2)];
            cjr[mt][so] = q.x;
            tir[mt][so] = __float_as_int(q.y);
        }
    float hpr[2][2], hnr[2][2];
    #pragma unroll
    for (int mt = 0; mt < 2; mt++)
        #pragma unroll
        for (int so = 0; so < 2; so++) { hpr[mt][so] = -3.4e38f; hnr[mt][so] = 3.4e38f; }

    float* scrHp = (float*)(smem + OFF_B);
    float* scrHn = (float*)(smem + OFF_B + SCR_HN_OFF);
    const int g8 = wm * 4 + (lane >> 3);           // 0..7 after prefold
    const bool keep = ((lane >> 2) & 1) == 0;

    #pragma unroll
    for (int n8 = 0; n8 < 4; n8++) {
        #pragma unroll
        for (int par = 0; par < 2; par++) {
            const int colL = wn * 32 + n8 * 8 + (lane & 3) * 2 + par;
            float2 qc = scjc[colL];
            float cjc = qc.x;
            int   tjc = __float_as_int(qc.y);
            float hpc = -3.4e38f, hnc = 3.4e38f;
            #pragma unroll
            for (int mt = 0; mt < 2; mt++)
                #pragma unroll
                for (int so = 0; so < 2; so++) {
                    float d = -2.0f * acc[mt][n8][so * 2 + par];
                    float tvr = d + cjc;
                    float tvc = d + cjr[mt][so];
                    if (tjc == tir[mt][so]) {
                        hpr[mt][so] = fmaxf(hpr[mt][so], tvr);
                        hpc         = fmaxf(hpc,         tvc);
                    } else {
                        hnr[mt][so] = fminf(hnr[mt][so], tvr);
                        hnc         = fminf(hnc,         tvc);
                    }
                }
            hpc = fmaxf(hpc, __shfl_xor_sync(0xffffffffu, hpc, 4));
            hnc = fminf(hnc, __shfl_xor_sync(0xffffffffu, hnc, 4));
            if (keep) {
                scrHp[colL * SCR9 + g8] = hpc;
                scrHn[colL * SCR9 + g8] = hnc;
            }
        }
    }

    // row fold across the 4 column-lanes, write slot (bj, sub=wn)
    #pragma unroll
    for (int o = 1; o <= 2; o <<= 1)
        #pragma unroll
        for (int mt = 0; mt < 2; mt++)
            #pragma unroll
            for (int so = 0; so < 2; so++) {
                hpr[mt][so] = fmaxf(hpr[mt][so], __shfl_xor_sync(0xffffffffu, hpr[mt][so], o));
                hnr[mt][so] = fminf(hnr[mt][so], __shfl_xor_sync(0xffffffffu, hnr[mt][so], o));
            }
    if ((lane & 3) == 0) {
        #pragma unroll
        for (int mt = 0; mt < 2; mt++)
            #pragma unroll
            for (int so = 0; so < 2; so++) {
                int r = bi * TILE_M + wm * 32 + mt * 16 + so * 8 + (lane >> 2);
                g_php[((bj * NSUB) + wn) * NPTS + r] = hpr[mt][so];
                g_phn[((bj * NSUB) + wn) * NPTS + r] = hnr[mt][so];
            }
    }

    __syncthreads();   // scratch fully written

    // col fold: tid<128 folds hp for column tid; tid in [128,256) folds hn
    {
        int colL = tid & 127;
        const int slot = ((bi >> 1) * NSUB) + 4 + (bi & 1);
        if (tid < 128) {
            float v = scrHp[colL * SCR9];
            #pragma unroll
            for (int gq = 1; gq < 8; gq++) v = fmaxf(v, scrHp[colL * SCR9 + gq]);
            g_php[slot * NPTS + bj * TILE_N + colL] = v;
        } else {
            float v = scrHn[colL * SCR9];
            #pragma unroll
            for (int gq = 1; gq < 8; gq++) v = fminf(v, scrHn[colL * SCR9 + gq]);
            g_phn[slot * NPTS + bj * TILE_N + colL] = v;
        }
    }
}

// ---------------- fused merge: slots -> loss -> mean (last block done) ----
__global__ void merge_kernel(float* __restrict__ out) {
    __shared__ float ssum[128];
    __shared__ float sfin[2];
    __shared__ bool  last;
    int r = blockIdx.x * 128 + threadIdx.x;
    int blk = r >> 7;          // 128-col block index of anchor r
    float hp = -3.4e38f, hn = 3.4e38f;
    for (int o = 0; o < 64; o++) {
        const float* php = g_php + (size_t)o * NSUB * NPTS + r;
        const float* phn = g_phn + (size_t)o * NSUB * NPTS + r;
        if (o >= blk) {
            #pragma unroll
            for (int su = 0; su < 4; su++) {
                hp = fmaxf(hp, php[(size_t)su * NPTS]);
                hn = fminf(hn, phn[(size_t)su * NPTS]);
            }
        }
        if (o <= blk) {
            #pragma unroll
            for (int su = 4; su < 6; su++) {
                hp = fmaxf(hp, php[(size_t)su * NPTS]);
                hn = fminf(hn, phn[(size_t)su * NPTS]);
            }
        }
    }
    float ci = g_ci[r];
    float hpd = sqrtf(fmaxf(ci + hp, 0.0f));
    float hnd = sqrtf(fmaxf(ci + hn, 0.0f));
    ssum[threadIdx.x] = fmaxf(hpd - hnd + MARGIN, 0.0f);
    __syncthreads();
    for (int o = 64; o; o >>= 1) {
        if (threadIdx.x < o) ssum[threadIdx.x] += ssum[threadIdx.x + o];
        __syncthreads();
    }
    if (threadIdx.x == 0) {
        g_bsum[blockIdx.x] = ssum[0];
        __threadfence();
        int prev = atomicAdd(&g_cnt, 1);
        last = (prev == gridDim.x - 1);
    }
    __syncthreads();
    if (last) {
        if (threadIdx.x < 64) {
            float v = g_bsum[threadIdx.x];
            #pragma unroll
            for (int o = 16; o; o >>= 1) v += __shfl_xor_sync(0xffffffffu, v, o);
            if ((threadIdx.x & 31) == 0) sfin[threadIdx.x >> 5] = v;
        }
        __syncthreads();
        if (threadIdx.x == 0) {
            out[0] = (sfin[0] + sfin[1]) / (float)NPTS;
            g_cnt = 0;   // reset for next graph replay
        }
    }
}

extern "C" void kernel_launch(void* const* d_in, const int* in_sizes, int n_in,
                              void* d_out, int out_size) {
    const float* x   = (const float*)d_in[0];
    const int*   tgt = (const int*)d_in[1];
    float*       out = (float*)d_out;

    precompute_kernel<<<256, 256>>>(x);

    cudaFuncSetAttribute(tile_kernel,
                         cudaFuncAttributeMaxDynamicSharedMemorySize, SMEM_BYTES);
    tile_kernel<<<NCTAS, 256, SMEM_BYTES>>>(tgt);

    merge_kernel<<<NPTS / 128, 128>>>(out);
}